// round 4
// baseline (speedup 1.0000x reference)
#include <cuda_runtime.h>

// Shapes (fixed by the problem)
#define BB 2
#define NN 2048
#define CC 1024
#define HH 16
#define HD 64
#define MTOT (BB*NN)          // 4096
#define QKVN (3*CC)           // 3072
#define OUT_ATTN (BB*NN*CC)   // 4194304 floats: out (B,N,C)
#define PRES_HALF (BB*HH*NN*HD) // 4194304 floats per K/V half of present
#define NTILES (NN/64)        // 32

// Scratch (device globals: allocation-free)
__device__ float g_q[BB*HH*NN*HD];     // 16 MB: scaled Q, (b,h,n,d)
__device__ float g_attn[BB*NN*CC];     // 16 MB: attention output (b,n,c)
__device__ unsigned char g_mask[BB*NN];
__device__ unsigned char g_tile_valid[BB*NTILES];
__device__ int g_cs;

// ---------------------------------------------------------------------------
// Prep: normalize padding mask (handles bool-u8 / int32 / float32 storage),
// read causal_start (handles int or float bit patterns), per-tile validity.
// ---------------------------------------------------------------------------
__global__ void k_prep(const unsigned char* __restrict__ mraw,
                       const int* __restrict__ csp) {
    __shared__ int s_byte;
    const int tid = threadIdx.x;
    if (tid == 0) {
        int v = csp[0];
        if (v < 0 || v > NN) {            // looks like float bits
            float f = __int_as_float(v);
            v = (int)f;
            if (v < 0) v = 0;
            if (v > NN) v = NN;
        }
        g_cs = v;
        s_byte = 0;
    }
    __syncthreads();
    // Detect byte-packed bools: only safe read span is B*N bytes. If the data
    // were 4-byte words, the first B*N bytes cover elements 0..B*N/4-1, which
    // are all zero for tail-padding; any nonzero byte => byte-packed bools.
    int any = 0;
    for (int i = tid; i < BB*NN; i += 256) any |= mraw[i];
    if (any) atomicOr(&s_byte, 1);
    __syncthreads();
    const int bytemode = s_byte;
    const int* mw = (const int*)mraw;
    for (int e = tid; e < BB*NN; e += 256) {
        unsigned char p = bytemode ? (unsigned char)(mraw[e] != 0)
                                   : (unsigned char)(mw[e] != 0);
        g_mask[e] = p;
    }
    __syncthreads();
    for (int t = tid; t < BB*NTILES; t += 256) {
        const int b = t / NTILES, kt = t % NTILES;
        const unsigned char* row = g_mask + b*NN + kt*64;
        unsigned char anyv = 0;
        #pragma unroll 8
        for (int j = 0; j < 64; j++) anyv |= (unsigned char)(row[j] == 0);
        g_tile_valid[t] = anyv;
    }
}

// ---------------------------------------------------------------------------
// GEMM 1: qkv = x @ w_qkv^T  (both row-major, dot over contiguous K)
// 128x128 tile, BK=16, 256 threads, 8x8 per thread split as 2x(4+4).
// Epilogue scatters q -> g_q, k/v -> present region of d_out.
// ---------------------------------------------------------------------------
__global__ __launch_bounds__(256) void k_gemm_qkv(const float* __restrict__ A,
                                                  const float* __restrict__ Bm,
                                                  float* __restrict__ outp) {
    __shared__ float As[16][132];
    __shared__ float Bs[16][132];
    const int tid = threadIdx.x;
    const int tx = tid & 15, ty = tid >> 4;
    const int m0 = blockIdx.y * 128, n0 = blockIdx.x * 128;
    const int lr = tid >> 1;            // 0..127
    const int lk = (tid & 1) * 8;       // 0 or 8
    const float* ag = A  + (m0 + lr) * CC + lk;
    const float* bg = Bm + (n0 + lr) * CC + lk;

    float acc[8][8];
    #pragma unroll
    for (int i = 0; i < 8; i++)
        #pragma unroll
        for (int j = 0; j < 8; j++) acc[i][j] = 0.f;

    for (int kb = 0; kb < CC; kb += 16) {
        const float4 a0 = *(const float4*)(ag + kb);
        const float4 a1 = *(const float4*)(ag + kb + 4);
        const float4 b0 = *(const float4*)(bg + kb);
        const float4 b1 = *(const float4*)(bg + kb + 4);
        __syncthreads();
        As[lk+0][lr]=a0.x; As[lk+1][lr]=a0.y; As[lk+2][lr]=a0.z; As[lk+3][lr]=a0.w;
        As[lk+4][lr]=a1.x; As[lk+5][lr]=a1.y; As[lk+6][lr]=a1.z; As[lk+7][lr]=a1.w;
        Bs[lk+0][lr]=b0.x; Bs[lk+1][lr]=b0.y; Bs[lk+2][lr]=b0.z; Bs[lk+3][lr]=b0.w;
        Bs[lk+4][lr]=b1.x; Bs[lk+5][lr]=b1.y; Bs[lk+6][lr]=b1.z; Bs[lk+7][lr]=b1.w;
        __syncthreads();
        #pragma unroll
        for (int k = 0; k < 16; k++) {
            const float4 aA = *(const float4*)&As[k][ty*4];
            const float4 aB = *(const float4*)&As[k][64 + ty*4];
            const float4 bA = *(const float4*)&Bs[k][tx*4];
            const float4 bB = *(const float4*)&Bs[k][64 + tx*4];
            const float av[8] = {aA.x,aA.y,aA.z,aA.w, aB.x,aB.y,aB.z,aB.w};
            const float bv[8] = {bA.x,bA.y,bA.z,bA.w, bB.x,bB.y,bB.z,bB.w};
            #pragma unroll
            for (int i = 0; i < 8; i++)
                #pragma unroll
                for (int j = 0; j < 8; j++) acc[i][j] += av[i] * bv[j];
        }
    }

    // scatter epilogue: n -> (s, h, d); m -> (b, nq)
    #pragma unroll
    for (int jh = 0; jh < 2; jh++) {
        const int nc0 = n0 + jh*64 + tx*4;       // 4-aligned, never crosses 64
        const int s  = nc0 >> 10;
        const int h  = (nc0 >> 6) & (HH - 1);
        const int db = nc0 & (HD - 1);
        float* base = (s == 0) ? g_q : (outp + OUT_ATTN + (s - 1) * PRES_HALF);
        #pragma unroll
        for (int ih = 0; ih < 2; ih++) {
            #pragma unroll
            for (int i = 0; i < 4; i++) {
                const int m = m0 + ih*64 + ty*4 + i;
                const int b = m >> 11, nq = m & (NN - 1);
                float* dst = base + (((b*HH + h)*NN + nq)*HD + db);
                *(float4*)dst = make_float4(acc[ih*4+i][jh*4+0], acc[ih*4+i][jh*4+1],
                                            acc[ih*4+i][jh*4+2], acc[ih*4+i][jh*4+3]);
            }
        }
    }
}

// ---------------------------------------------------------------------------
// GEMM 2: out = g_attn @ w_proj^T + b_proj
// ---------------------------------------------------------------------------
__global__ __launch_bounds__(256) void k_gemm_proj(const float* __restrict__ Bm,
                                                   const float* __restrict__ bias,
                                                   float* __restrict__ outp) {
    __shared__ float As[16][132];
    __shared__ float Bs[16][132];
    const int tid = threadIdx.x;
    const int tx = tid & 15, ty = tid >> 4;
    const int m0 = blockIdx.y * 128, n0 = blockIdx.x * 128;
    const int lr = tid >> 1;
    const int lk = (tid & 1) * 8;
    const float* ag = g_attn + (m0 + lr) * CC + lk;
    const float* bg = Bm + (n0 + lr) * CC + lk;

    float acc[8][8];
    #pragma unroll
    for (int i = 0; i < 8; i++)
        #pragma unroll
        for (int j = 0; j < 8; j++) acc[i][j] = 0.f;

    for (int kb = 0; kb < CC; kb += 16) {
        const float4 a0 = *(const float4*)(ag + kb);
        const float4 a1 = *(const float4*)(ag + kb + 4);
        const float4 b0 = *(const float4*)(bg + kb);
        const float4 b1 = *(const float4*)(bg + kb + 4);
        __syncthreads();
        As[lk+0][lr]=a0.x; As[lk+1][lr]=a0.y; As[lk+2][lr]=a0.z; As[lk+3][lr]=a0.w;
        As[lk+4][lr]=a1.x; As[lk+5][lr]=a1.y; As[lk+6][lr]=a1.z; As[lk+7][lr]=a1.w;
        Bs[lk+0][lr]=b0.x; Bs[lk+1][lr]=b0.y; Bs[lk+2][lr]=b0.z; Bs[lk+3][lr]=b0.w;
        Bs[lk+4][lr]=b1.x; Bs[lk+5][lr]=b1.y; Bs[lk+6][lr]=b1.z; Bs[lk+7][lr]=b1.w;
        __syncthreads();
        #pragma unroll
        for (int k = 0; k < 16; k++) {
            const float4 aA = *(const float4*)&As[k][ty*4];
            const float4 aB = *(const float4*)&As[k][64 + ty*4];
            const float4 bA = *(const float4*)&Bs[k][tx*4];
            const float4 bB = *(const float4*)&Bs[k][64 + tx*4];
            const float av[8] = {aA.x,aA.y,aA.z,aA.w, aB.x,aB.y,aB.z,aB.w};
            const float bv[8] = {bA.x,bA.y,bA.z,bA.w, bB.x,bB.y,bB.z,bB.w};
            #pragma unroll
            for (int i = 0; i < 8; i++)
                #pragma unroll
                for (int j = 0; j < 8; j++) acc[i][j] += av[i] * bv[j];
        }
    }

    #pragma unroll
    for (int jh = 0; jh < 2; jh++) {
        const int nc0 = n0 + jh*64 + tx*4;
        const float4 bz = *(const float4*)(bias + nc0);
        #pragma unroll
        for (int ih = 0; ih < 2; ih++) {
            #pragma unroll
            for (int i = 0; i < 4; i++) {
                const int m = m0 + ih*64 + ty*4 + i;
                *(float4*)(outp + m*CC + nc0) =
                    make_float4(acc[ih*4+i][jh*4+0] + bz.x, acc[ih*4+i][jh*4+1] + bz.y,
                                acc[ih*4+i][jh*4+2] + bz.z, acc[ih*4+i][jh*4+3] + bz.w);
            }
        }
    }
}

// ---------------------------------------------------------------------------
// Flash attention, fp32. BM=BN=64, 256 threads (16x16 grid, 4x4 fragments).
// XOR swizzle (on row>>2, float4-group granularity) for Q/K/P smem so
// column-direction vector loads are at most 2-way bank conflicted.
// ---------------------------------------------------------------------------
__device__ __forceinline__ int swz4(int row, int c /*multiple of 4*/) {
    return row*64 + ((((c >> 2) ^ (row >> 2)) & 15) << 2);
}

__global__ __launch_bounds__(256) void k_attn(float* __restrict__ outp) {
    __shared__ float Qs[64*64];
    __shared__ float KPs[64*64];   // K tile during S-phase, P tile during O-phase
    __shared__ float Vs[64*64];
    const int tid = threadIdx.x;
    const int tj = tid & 15, ti = tid >> 4;
    const int qt = blockIdx.x, h = blockIdx.y, b = blockIdx.z;
    const int qs = qt * 64;
    const int cs = g_cs;
    const float* qg = g_q + ((b*HH + h)*NN + qs)*HD;
    const float* kg = outp + OUT_ATTN + ((b*HH + h)*NN)*HD;
    const float* vg = kg + PRES_HALF;

    // Load Q tile (pre-scaled by hd^-0.5 = 0.125)
    {
        const int llr = tid >> 4;          // 0..15
        const int lc = (tid & 15) * 4;     // 0..60
        #pragma unroll
        for (int p = 0; p < 4; p++) {
            const int r = llr + p*16;
            const float4 v = *(const float4*)(qg + r*HD + lc);
            *(float4*)&Qs[swz4(r, lc)] =
                make_float4(v.x*0.125f, v.y*0.125f, v.z*0.125f, v.w*0.125f);
        }
    }

    float m_i[4], l_i[4], o[4][4];
    #pragma unroll
    for (int r = 0; r < 4; r++) {
        m_i[r] = -1e30f; l_i[r] = 0.f;
        #pragma unroll
        for (int c = 0; c < 4; c++) o[r][c] = 0.f;
    }

    const int qend = qs + 63;
    for (int kt = 0; kt < NTILES; kt++) {
        const int ks = kt * 64;
        if (ks > qend && ks >= cs) break;          // no later tile can be allowed
        if (!g_tile_valid[b*NTILES + kt]) continue; // all keys padded

        __syncthreads();   // previous O-phase finished with KPs/Vs
        {
            const int llr = tid >> 4;
            const int lc = (tid & 15) * 4;
            #pragma unroll
            for (int p = 0; p < 4; p++) {
                const int r = llr + p*16;
                const float4 kv = *(const float4*)(kg + (ks + r)*HD + lc);
                *(float4*)&KPs[swz4(r, lc)] = kv;
                const float4 vv = *(const float4*)(vg + (ks + r)*HD + lc);
                *(float4*)&Vs[r*64 + lc] = vv;
            }
        }
        unsigned char pj[4];
        #pragma unroll
        for (int c = 0; c < 4; c++) pj[c] = g_mask[b*NN + ks + tj*4 + c];
        __syncthreads();

        // ---- S = Q K^T (thread fragment 4x4) ----
        float s[4][4];
        #pragma unroll
        for (int r = 0; r < 4; r++)
            #pragma unroll
            for (int c = 0; c < 4; c++) s[r][c] = 0.f;
        #pragma unroll
        for (int d0 = 0; d0 < 64; d0 += 4) {
            float4 q4[4], k4[4];
            #pragma unroll
            for (int r = 0; r < 4; r++) q4[r] = *(const float4*)&Qs[swz4(ti*4+r, d0)];
            #pragma unroll
            for (int c = 0; c < 4; c++) k4[c] = *(const float4*)&KPs[swz4(tj*4+c, d0)];
            #pragma unroll
            for (int r = 0; r < 4; r++)
                #pragma unroll
                for (int c = 0; c < 4; c++)
                    s[r][c] += q4[r].x*k4[c].x + q4[r].y*k4[c].y
                             + q4[r].z*k4[c].z + q4[r].w*k4[c].w;
        }

        // ---- mask + online softmax (row stats in registers; 16-lane shfl) ----
        float alpha[4];
        #pragma unroll
        for (int r = 0; r < 4; r++) {
            const int iq = qs + ti*4 + r;
            float mloc = -1e30f;
            #pragma unroll
            for (int c = 0; c < 4; c++) {
                const int j = ks + tj*4 + c;
                const bool ok = (pj[c] == 0) && ((j <= iq) || (j < cs));
                if (!ok) s[r][c] = -1e30f;
                mloc = fmaxf(mloc, s[r][c]);
            }
            #pragma unroll
            for (int off = 8; off > 0; off >>= 1)
                mloc = fmaxf(mloc, __shfl_xor_sync(0xffffffffu, mloc, off));
            const float mnew = fmaxf(m_i[r], mloc);
            float sum = 0.f;
            #pragma unroll
            for (int c = 0; c < 4; c++) {
                const float p = __expf(s[r][c] - mnew);
                s[r][c] = p;
                sum += p;
            }
            #pragma unroll
            for (int off = 8; off > 0; off >>= 1)
                sum += __shfl_xor_sync(0xffffffffu, sum, off);
            alpha[r] = __expf(m_i[r] - mnew);
            l_i[r] = l_i[r] * alpha[r] + sum;
            m_i[r] = mnew;
        }

        __syncthreads();   // all S-phase reads of KPs done -> safe to overwrite with P
        // store P transposed: P[i][j] at KPs[j][i] (swizzled on i-groups)
        #pragma unroll
        for (int c = 0; c < 4; c++) {
            const int jl = tj*4 + c;
            #pragma unroll
            for (int r = 0; r < 4; r++)
                KPs[jl*64 + (((ti ^ (jl >> 2)) & 15) << 2) + r] = s[r][c];
        }
        __syncthreads();

        // ---- O = alpha*O + P V ----
        #pragma unroll
        for (int r = 0; r < 4; r++)
            #pragma unroll
            for (int c = 0; c < 4; c++) o[r][c] *= alpha[r];
        #pragma unroll 8
        for (int j = 0; j < 64; j++) {
            const float4 p4 = *(const float4*)&KPs[j*64 + (((ti ^ (j >> 2)) & 15) << 2)];
            const float4 v4 = *(const float4*)&Vs[j*64 + tj*4];
            const float pa[4] = {p4.x, p4.y, p4.z, p4.w};
            const float va[4] = {v4.x, v4.y, v4.z, v4.w};
            #pragma unroll
            for (int r = 0; r < 4; r++)
                #pragma unroll
                for (int c = 0; c < 4; c++)
                    o[r][c] += pa[r] * va[c];
        }
    }

    // finalize + write to g_attn (b, n, h*HD + d)
    #pragma unroll
    for (int r = 0; r < 4; r++) {
        const float inv = 1.0f / l_i[r];
        const int row = b*NN + qs + ti*4 + r;
        *(float4*)&g_attn[row*CC + h*HD + tj*4] =
            make_float4(o[r][0]*inv, o[r][1]*inv, o[r][2]*inv, o[r][3]*inv);
    }
}

// ---------------------------------------------------------------------------
extern "C" void kernel_launch(void* const* d_in, const int* in_sizes, int n_in,
                              void* d_out, int out_size) {
    (void)in_sizes; (void)n_in; (void)out_size;
    const float* x      = (const float*)d_in[0];
    const unsigned char* mask = (const unsigned char*)d_in[1];
    const int*   csp    = (const int*)d_in[2];
    const float* w_qkv  = (const float*)d_in[3];
    const float* w_proj = (const float*)d_in[4];
    const float* b_proj = (const float*)d_in[5];
    float* outp = (float*)d_out;

    k_prep<<<1, 256>>>(mask, csp);

    dim3 g1(QKVN / 128, MTOT / 128);     // (24, 32)
    k_gemm_qkv<<<g1, 256>>>(x, w_qkv, outp);

    dim3 ga(NN / 64, HH, BB);            // (32, 16, 2)
    k_attn<<<ga, 256>>>(outp);

    dim3 g2(CC / 128, MTOT / 128);       // (8, 32)
    k_gemm_proj<<<g2, 256>>>(w_proj, b_proj, outp);
}

// round 8
// speedup vs baseline: 1.4120x; 1.4120x over previous
#include <cuda_runtime.h>
#include <cuda_bf16.h>
#include <cstdint>

// Shapes (fixed by the problem)
#define BB 2
#define NN 2048
#define CC 1024
#define HH 16
#define HD 64
#define MTOT (BB*NN)            // 4096
#define QKVN (3*CC)             // 3072
#define OUT_ATTN (BB*NN*CC)     // out (B,N,C) floats
#define PRES_HALF (BB*HH*NN*HD) // per K/V half of present
#define NTILES (NN/64)          // 32
#define NKB 16                  // 1024 / 64 K-blocks

// Scratch (device globals: allocation-free)
__device__ float g_q[BB*HH*NN*HD];
__device__ float g_attn[BB*NN*CC];
__device__ unsigned char g_mask[BB*NN];
__device__ unsigned char g_tile_valid[BB*NTILES];
__device__ int g_cs;

// bf16 hi/lo split scratch
__device__ __nv_bfloat16 g_xh[MTOT*CC],  g_xl[MTOT*CC];
__device__ __nv_bfloat16 g_wqh[QKVN*CC], g_wql[QKVN*CC];
__device__ __nv_bfloat16 g_wph[CC*CC],   g_wpl[CC*CC];
__device__ __nv_bfloat16 g_ah[MTOT*CC],  g_al[MTOT*CC];

// ---------------------------------------------------------------------------
// Baseline-PTX helpers (valid on compute_103 without the 'a' feature target)
// ---------------------------------------------------------------------------
__device__ __forceinline__ uint32_t smem_u32(const void* p) {
    uint32_t a;
    asm("{ .reg .u64 t; cvta.to.shared.u64 t, %1; cvt.u32.u64 %0, t; }"
        : "=r"(a) : "l"(p));
    return a;
}
__device__ __forceinline__ void cpasync16(uint32_t s, const void* g) {
    asm volatile("cp.async.cg.shared.global [%0], [%1], 16;" :: "r"(s), "l"(g));
}
__device__ __forceinline__ void cp_commit() {
    asm volatile("cp.async.commit_group;" ::: "memory");
}
template <int N>
__device__ __forceinline__ void cp_wait() {
    asm volatile("cp.async.wait_group %0;" :: "n"(N) : "memory");
}
__device__ __forceinline__ void ldm4(uint32_t* r, uint32_t a) {
    asm volatile("ldmatrix.sync.aligned.m8n8.x4.shared.b16 {%0,%1,%2,%3}, [%4];"
                 : "=r"(r[0]), "=r"(r[1]), "=r"(r[2]), "=r"(r[3]) : "r"(a));
}
__device__ __forceinline__ void ldm2(uint32_t* r, uint32_t a) {
    asm volatile("ldmatrix.sync.aligned.m8n8.x2.shared.b16 {%0,%1}, [%2];"
                 : "=r"(r[0]), "=r"(r[1]) : "r"(a));
}
__device__ __forceinline__ void mma_bf16(float* d, const uint32_t* a, const uint32_t* b) {
    asm volatile(
        "mma.sync.aligned.m16n8k16.row.col.f32.bf16.bf16.f32 "
        "{%0,%1,%2,%3}, {%4,%5,%6,%7}, {%8,%9}, {%0,%1,%2,%3};"
        : "+f"(d[0]), "+f"(d[1]), "+f"(d[2]), "+f"(d[3])
        : "r"(a[0]), "r"(a[1]), "r"(a[2]), "r"(a[3]), "r"(b[0]), "r"(b[1]));
}

// ---------------------------------------------------------------------------
// Prep: normalize padding mask + causal_start + per-tile validity.
// ---------------------------------------------------------------------------
__global__ void k_prep(const unsigned char* __restrict__ mraw,
                       const int* __restrict__ csp) {
    __shared__ int s_byte;
    const int tid = threadIdx.x;
    if (tid == 0) {
        int v = csp[0];
        if (v < 0 || v > NN) {
            float f = __int_as_float(v);
            v = (int)f;
            if (v < 0) v = 0;
            if (v > NN) v = NN;
        }
        g_cs = v;
        s_byte = 0;
    }
    __syncthreads();
    int any = 0;
    for (int i = tid; i < BB*NN; i += 256) any |= mraw[i];
    if (any) atomicOr(&s_byte, 1);
    __syncthreads();
    const int bytemode = s_byte;
    const int* mw = (const int*)mraw;
    for (int e = tid; e < BB*NN; e += 256) {
        unsigned char p = bytemode ? (unsigned char)(mraw[e] != 0)
                                   : (unsigned char)(mw[e] != 0);
        g_mask[e] = p;
    }
    __syncthreads();
    for (int t = tid; t < BB*NTILES; t += 256) {
        const int b = t / NTILES, kt = t % NTILES;
        const unsigned char* row = g_mask + b*NN + kt*64;
        unsigned char anyv = 0;
        #pragma unroll 8
        for (int j = 0; j < 64; j++) anyv |= (unsigned char)(row[j] == 0);
        g_tile_valid[t] = anyv;
    }
}

// ---------------------------------------------------------------------------
// fp32 -> bf16 hi/lo split (hi = rn(x), lo = rn(x - hi))
// ---------------------------------------------------------------------------
__global__ void k_split(const float4* __restrict__ src,
                        __nv_bfloat162* __restrict__ hi,
                        __nv_bfloat162* __restrict__ lo) {
    const int i = blockIdx.x * 256 + threadIdx.x;
    const float4 v = src[i];
    const __nv_bfloat16 h0 = __float2bfloat16(v.x), h1 = __float2bfloat16(v.y),
                        h2 = __float2bfloat16(v.z), h3 = __float2bfloat16(v.w);
    const __nv_bfloat16 l0 = __float2bfloat16(v.x - __bfloat162float(h0)),
                        l1 = __float2bfloat16(v.y - __bfloat162float(h1)),
                        l2 = __float2bfloat16(v.z - __bfloat162float(h2)),
                        l3 = __float2bfloat16(v.w - __bfloat162float(h3));
    hi[2*i]   = __halves2bfloat162(h0, h1);
    hi[2*i+1] = __halves2bfloat162(h2, h3);
    lo[2*i]   = __halves2bfloat162(l0, l1);
    lo[2*i+1] = __halves2bfloat162(l2, l3);
}

// ---------------------------------------------------------------------------
// HMMA GEMM: C[M x N] = A[M x K] * B[N x K]^T via bf16 hi/lo 3-MMA split.
// CTA 128x128, BK=64, 8 warps (2m x 4n), warp tile 64x32, m16n8k16.
// Double-buffered cp.async smem (2 x 64KB). XOR-swizzled 16B chunks.
// mode 0: qkv scatter epilogue (q -> g_q, k/v -> present in d_out)
// mode 1: proj epilogue (out = C + bias)
// ---------------------------------------------------------------------------
#define TILE_B 16384          // one 128x64 bf16 tile
#define STAGE_B (4*TILE_B)    // Ah, Al, Bh, Bl

__global__ void __launch_bounds__(256, 1)
k_mma_gemm(const __nv_bfloat16* __restrict__ gAh, const __nv_bfloat16* __restrict__ gAl,
           const __nv_bfloat16* __restrict__ gBh, const __nv_bfloat16* __restrict__ gBl,
           const float* __restrict__ bias, float* __restrict__ outp, int mode) {
    extern __shared__ __align__(16) unsigned char dsm[];
    const int tid = threadIdx.x;
    const int lane = tid & 31, wid = tid >> 5;
    const int warpM = wid & 1, warpN = wid >> 1;     // 2 x 4 warp grid
    const int m0 = blockIdx.y * 128, n0 = blockIdx.x * 128;

    const uint32_t dyn0 = smem_u32(dsm);
    const uint32_t sbase = (dyn0 + 1023) & ~1023u;   // 1KB align

    // ---- loader mapping: each thread owns 4 x 16B chunks per tile ----
    const int lrow = tid >> 1;                 // 0..127
    const int lcj0 = (tid & 1) * 4;            // chunk 0..3 or 4..7
    const __nv_bfloat16* gptr[4] = {
        gAh + (size_t)(m0 + lrow) * CC, gAl + (size_t)(m0 + lrow) * CC,
        gBh + (size_t)(n0 + lrow) * CC, gBl + (size_t)(n0 + lrow) * CC };
    uint32_t soff[4][4];
    #pragma unroll
    for (int t = 0; t < 4; t++)
        #pragma unroll
        for (int j = 0; j < 4; j++)
            soff[t][j] = (uint32_t)(t * TILE_B + lrow * 128
                                    + (((lcj0 + j) ^ (lrow & 7)) << 4));

    // ---- fragment address components ----
    const int la = lane & 15, ka = lane >> 4;          // A ldmatrix.x4
    const int lb = lane & 7, kb2 = (lane >> 3) & 1;    // B ldmatrix.x2
    const int arow = warpM * 64 + la;                  // + mf*16
    const int brow = warpN * 32 + lb;                  // + nf*8
    const int ax = arow & 7, bx = brow & 7;

    float acc[4][4][4];
    #pragma unroll
    for (int mf = 0; mf < 4; mf++)
        #pragma unroll
        for (int nf = 0; nf < 4; nf++)
            #pragma unroll
            for (int i = 0; i < 4; i++) acc[mf][nf][i] = 0.f;

    // issue stage 0
    #pragma unroll
    for (int t = 0; t < 4; t++)
        #pragma unroll
        for (int j = 0; j < 4; j++)
            cpasync16(sbase + soff[t][j], gptr[t] + (lcj0 + j) * 8);
    cp_commit();

    for (int kb = 0; kb < NKB; kb++) {
        if (kb + 1 < NKB) {
            const uint32_t st = (uint32_t)((kb + 1) & 1) * STAGE_B;
            const size_t ko = (size_t)(kb + 1) * 64;
            #pragma unroll
            for (int t = 0; t < 4; t++)
                #pragma unroll
                for (int j = 0; j < 4; j++)
                    cpasync16(sbase + st + soff[t][j], gptr[t] + ko + (lcj0 + j) * 8);
            cp_commit();
            cp_wait<1>();
        } else {
            cp_wait<0>();
        }
        __syncthreads();

        const uint32_t buf = sbase + (uint32_t)(kb & 1) * STAGE_B;
        const uint32_t aAh = buf, aAl = buf + TILE_B;
        const uint32_t aBh = buf + 2*TILE_B, aBl = buf + 3*TILE_B;

        #pragma unroll
        for (int ks = 0; ks < 4; ks++) {
            const int kcB = ks * 2 + kb2;
            uint32_t Bh[4][2], Bl[4][2];
            #pragma unroll
            for (int nf = 0; nf < 4; nf++) {
                const uint32_t off = (uint32_t)((brow + nf*8) * 128 + ((kcB ^ bx) << 4));
                ldm2(Bh[nf], aBh + off);
                ldm2(Bl[nf], aBl + off);
            }
            const int kcA = ks * 2 + ka;
            #pragma unroll
            for (int mf = 0; mf < 4; mf++) {
                const uint32_t off = (uint32_t)((arow + mf*16) * 128 + ((kcA ^ ax) << 4));
                uint32_t Ah[4], Al[4];
                ldm4(Ah, aAh + off);
                ldm4(Al, aAl + off);
                #pragma unroll
                for (int nf = 0; nf < 4; nf++) {
                    mma_bf16(acc[mf][nf], Ah, Bh[nf]);
                    mma_bf16(acc[mf][nf], Ah, Bl[nf]);
                    mma_bf16(acc[mf][nf], Al, Bh[nf]);
                }
            }
        }
        __syncthreads();
    }

    // ---- epilogue: fragment (mf,nf): rows m_, m_+8; cols col, col+1 ----
    #pragma unroll
    for (int mf = 0; mf < 4; mf++) {
        #pragma unroll
        for (int nf = 0; nf < 4; nf++) {
            const float* a = acc[mf][nf];
            const int col = n0 + warpN*32 + nf*8 + 2*(lane & 3);
            const int m_  = m0 + warpM*64 + mf*16 + (lane >> 2);
            if (mode == 0) {
                const int s = col >> 10, h = (col >> 6) & 15, d0 = col & 63;
                float* base = (s == 0) ? g_q
                            : (outp + OUT_ATTN + (size_t)(s - 1) * PRES_HALF);
                const size_t hb = (size_t)((m_ >> 11) * HH + h) * NN;
                float* p1 = base + (hb + (m_ & (NN-1))) * HD + d0;
                float* p2 = base + (hb + ((m_ + 8) & (NN-1))) * HD + d0;
                *(float2*)p1 = make_float2(a[0], a[1]);
                *(float2*)p2 = make_float2(a[2], a[3]);
            } else {
                const float2 bz = *(const float2*)(bias + col);
                *(float2*)(outp + (size_t)m_ * CC + col) =
                    make_float2(a[0] + bz.x, a[1] + bz.y);
                *(float2*)(outp + (size_t)(m_ + 8) * CC + col) =
                    make_float2(a[2] + bz.x, a[3] + bz.y);
            }
        }
    }
}

// ---------------------------------------------------------------------------
// Flash attention, fp32 (unchanged). BM=BN=64, 256 threads.
// ---------------------------------------------------------------------------
__device__ __forceinline__ int swz4(int row, int c) {
    return row*64 + ((((c >> 2) ^ (row >> 2)) & 15) << 2);
}

__global__ void __launch_bounds__(256) k_attn(float* __restrict__ outp) {
    __shared__ float Qs[64*64];
    __shared__ float KPs[64*64];
    __shared__ float Vs[64*64];
    const int tid = threadIdx.x;
    const int tj = tid & 15, ti = tid >> 4;
    const int qt = blockIdx.x, h = blockIdx.y, b = blockIdx.z;
    const int qs = qt * 64;
    const int cs = g_cs;
    const float* qg = g_q + ((b*HH + h)*NN + qs)*HD;
    const float* kg = outp + OUT_ATTN + ((size_t)(b*HH + h)*NN)*HD;
    const float* vg = kg + PRES_HALF;

    {
        const int llr = tid >> 4;
        const int lc = (tid & 15) * 4;
        #pragma unroll
        for (int p = 0; p < 4; p++) {
            const int r = llr + p*16;
            const float4 v = *(const float4*)(qg + r*HD + lc);
            *(float4*)&Qs[swz4(r, lc)] =
                make_float4(v.x*0.125f, v.y*0.125f, v.z*0.125f, v.w*0.125f);
        }
    }

    float m_i[4], l_i[4], o[4][4];
    #pragma unroll
    for (int r = 0; r < 4; r++) {
        m_i[r] = -1e30f; l_i[r] = 0.f;
        #pragma unroll
        for (int c = 0; c < 4; c++) o[r][c] = 0.f;
    }

    const int qend = qs + 63;
    for (int kt = 0; kt < NTILES; kt++) {
        const int ks = kt * 64;
        if (ks > qend && ks >= cs) break;
        if (!g_tile_valid[b*NTILES + kt]) continue;

        __syncthreads();
        {
            const int llr = tid >> 4;
            const int lc = (tid & 15) * 4;
            #pragma unroll
            for (int p = 0; p < 4; p++) {
                const int r = llr + p*16;
                const float4 kv = *(const float4*)(kg + (size_t)(ks + r)*HD + lc);
                *(float4*)&KPs[swz4(r, lc)] = kv;
                const float4 vv = *(const float4*)(vg + (size_t)(ks + r)*HD + lc);
                *(float4*)&Vs[r*64 + lc] = vv;
            }
        }
        unsigned char pj[4];
        #pragma unroll
        for (int c = 0; c < 4; c++) pj[c] = g_mask[b*NN + ks + tj*4 + c];
        __syncthreads();

        float s[4][4];
        #pragma unroll
        for (int r = 0; r < 4; r++)
            #pragma unroll
            for (int c = 0; c < 4; c++) s[r][c] = 0.f;
        #pragma unroll
        for (int d0 = 0; d0 < 64; d0 += 4) {
            float4 q4[4], k4[4];
            #pragma unroll
            for (int r = 0; r < 4; r++) q4[r] = *(const float4*)&Qs[swz4(ti*4+r, d0)];
            #pragma unroll
            for (int c = 0; c < 4; c++) k4[c] = *(const float4*)&KPs[swz4(tj*4+c, d0)];
            #pragma unroll
            for (int r = 0; r < 4; r++)
                #pragma unroll
                for (int c = 0; c < 4; c++)
                    s[r][c] += q4[r].x*k4[c].x + q4[r].y*k4[c].y
                             + q4[r].z*k4[c].z + q4[r].w*k4[c].w;
        }

        float alpha[4];
        #pragma unroll
        for (int r = 0; r < 4; r++) {
            const int iq = qs + ti*4 + r;
            float mloc = -1e30f;
            #pragma unroll
            for (int c = 0; c < 4; c++) {
                const int j = ks + tj*4 + c;
                const bool ok = (pj[c] == 0) && ((j <= iq) || (j < cs));
                if (!ok) s[r][c] = -1e30f;
                mloc = fmaxf(mloc, s[r][c]);
            }
            #pragma unroll
            for (int off = 8; off > 0; off >>= 1)
                mloc = fmaxf(mloc, __shfl_xor_sync(0xffffffffu, mloc, off));
            const float mnew = fmaxf(m_i[r], mloc);
            float sum = 0.f;
            #pragma unroll
            for (int c = 0; c < 4; c++) {
                const float p = __expf(s[r][c] - mnew);
                s[r][c] = p;
                sum += p;
            }
            #pragma unroll
            for (int off = 8; off > 0; off >>= 1)
                sum += __shfl_xor_sync(0xffffffffu, sum, off);
            alpha[r] = __expf(m_i[r] - mnew);
            l_i[r] = l_i[r] * alpha[r] + sum;
            m_i[r] = mnew;
        }

        __syncthreads();
        #pragma unroll
        for (int c = 0; c < 4; c++) {
            const int jl = tj*4 + c;
            #pragma unroll
            for (int r = 0; r < 4; r++)
                KPs[jl*64 + (((ti ^ (jl >> 2)) & 15) << 2) + r] = s[r][c];
        }
        __syncthreads();

        #pragma unroll
        for (int r = 0; r < 4; r++)
            #pragma unroll
            for (int c = 0; c < 4; c++) o[r][c] *= alpha[r];
        #pragma unroll 8
        for (int j = 0; j < 64; j++) {
            const float4 p4 = *(const float4*)&KPs[j*64 + (((ti ^ (j >> 2)) & 15) << 2)];
            const float4 v4 = *(const float4*)&Vs[j*64 + tj*4];
            const float pa[4] = {p4.x, p4.y, p4.z, p4.w};
            const float va[4] = {v4.x, v4.y, v4.z, v4.w};
            #pragma unroll
            for (int r = 0; r < 4; r++)
                #pragma unroll
                for (int c = 0; c < 4; c++)
                    o[r][c] += pa[r] * va[c];
        }
    }

    #pragma unroll
    for (int r = 0; r < 4; r++) {
        const float inv = 1.0f / l_i[r];
        const int row = b*NN + qs + ti*4 + r;
        *(float4*)&g_attn[(size_t)row*CC + h*HD + tj*4] =
            make_float4(o[r][0]*inv, o[r][1]*inv, o[r][2]*inv, o[r][3]*inv);
    }
}

// ---------------------------------------------------------------------------
extern "C" void kernel_launch(void* const* d_in, const int* in_sizes, int n_in,
                              void* d_out, int out_size) {
    (void)in_sizes; (void)n_in; (void)out_size;
    const float* x      = (const float*)d_in[0];
    const unsigned char* mask = (const unsigned char*)d_in[1];
    const int*   csp    = (const int*)d_in[2];
    const float* w_qkv  = (const float*)d_in[3];
    const float* w_proj = (const float*)d_in[4];
    const float* b_proj = (const float*)d_in[5];
    float* outp = (float*)d_out;

    const int DSM = 2 * STAGE_B + 1024;    // 132 KB
    cudaFuncSetAttribute((const void*)k_mma_gemm,
                         cudaFuncAttributeMaxDynamicSharedMemorySize, DSM);

    __nv_bfloat16 *xh, *xl, *wqh, *wql, *wph, *wpl, *ah, *al;
    cudaGetSymbolAddress((void**)&xh,  g_xh);  cudaGetSymbolAddress((void**)&xl,  g_xl);
    cudaGetSymbolAddress((void**)&wqh, g_wqh); cudaGetSymbolAddress((void**)&wql, g_wql);
    cudaGetSymbolAddress((void**)&wph, g_wph); cudaGetSymbolAddress((void**)&wpl, g_wpl);
    cudaGetSymbolAddress((void**)&ah,  g_ah);  cudaGetSymbolAddress((void**)&al,  g_al);
    float* gattn;
    cudaGetSymbolAddress((void**)&gattn, g_attn);

    k_prep<<<1, 256>>>(mask, csp);

    k_split<<<MTOT*CC/1024, 256>>>((const float4*)x,
                                   (__nv_bfloat162*)xh, (__nv_bfloat162*)xl);
    k_split<<<QKVN*CC/1024, 256>>>((const float4*)w_qkv,
                                   (__nv_bfloat162*)wqh, (__nv_bfloat162*)wql);
    k_split<<<CC*CC/1024, 256>>>((const float4*)w_proj,
                                 (__nv_bfloat162*)wph, (__nv_bfloat162*)wpl);

    dim3 g1(QKVN / 128, MTOT / 128);          // (24, 32)
    k_mma_gemm<<<g1, 256, DSM>>>(xh, xl, wqh, wql, nullptr, outp, 0);

    dim3 ga(NN / 64, HH, BB);                 // (32, 16, 2)
    k_attn<<<ga, 256>>>(outp);

    k_split<<<MTOT*CC/1024, 256>>>((const float4*)gattn,
                                   (__nv_bfloat162*)ah, (__nv_bfloat162*)al);

    dim3 g2(CC / 128, MTOT / 128);            // (8, 32)
    k_mma_gemm<<<g2, 256, DSM>>>(ah, al, wph, wpl, b_proj, outp, 1);
}

// round 9
// speedup vs baseline: 2.3427x; 1.6592x over previous
#include <cuda_runtime.h>
#include <cuda_bf16.h>
#include <cstdint>

// Shapes (fixed by the problem)
#define BB 2
#define NN 2048
#define CC 1024
#define HH 16
#define HD 64
#define MTOT (BB*NN)            // 4096
#define QKVN (3*CC)             // 3072
#define OUT_ATTN (BB*NN*CC)     // out (B,N,C) floats
#define PRES_HALF (BB*HH*NN*HD) // per K/V half of present
#define NTILES (NN/64)          // 32 key tiles of 64
#define NKB 16                  // 1024 / 64 K-blocks (GEMM)

// Scratch (device globals: allocation-free)
__device__ unsigned char g_mask[BB*NN];
__device__ unsigned long long g_mbits[BB*NTILES];  // bit j = key valid
__device__ int g_cs;

// bf16 hi/lo operands
__device__ __nv_bfloat16 g_xh[MTOT*CC],  g_xl[MTOT*CC];
__device__ __nv_bfloat16 g_wqh[QKVN*CC], g_wql[QKVN*CC];
__device__ __nv_bfloat16 g_wph[CC*CC],   g_wpl[CC*CC];
__device__ __nv_bfloat16 g_ah[MTOT*CC],  g_al[MTOT*CC];   // attn out (proj A)
// q/k/v in (b,h,n,d), bf16 hi/lo (q pre-scaled by 0.125)
__device__ __nv_bfloat16 g_qh[PRES_HALF], g_ql[PRES_HALF];
__device__ __nv_bfloat16 g_kh[PRES_HALF], g_kl[PRES_HALF];
__device__ __nv_bfloat16 g_vh[PRES_HALF], g_vl[PRES_HALF];

// ---------------------------------------------------------------------------
// Baseline-PTX helpers (valid on compute_103)
// ---------------------------------------------------------------------------
__device__ __forceinline__ uint32_t smem_u32(const void* p) {
    uint32_t a;
    asm("{ .reg .u64 t; cvta.to.shared.u64 t, %1; cvt.u32.u64 %0, t; }"
        : "=r"(a) : "l"(p));
    return a;
}
__device__ __forceinline__ void cpasync16(uint32_t s, const void* g) {
    asm volatile("cp.async.cg.shared.global [%0], [%1], 16;" :: "r"(s), "l"(g));
}
__device__ __forceinline__ void cp_commit() {
    asm volatile("cp.async.commit_group;" ::: "memory");
}
template <int N>
__device__ __forceinline__ void cp_wait() {
    asm volatile("cp.async.wait_group %0;" :: "n"(N) : "memory");
}
__device__ __forceinline__ void ldm4(uint32_t* r, uint32_t a) {
    asm volatile("ldmatrix.sync.aligned.m8n8.x4.shared.b16 {%0,%1,%2,%3}, [%4];"
                 : "=r"(r[0]), "=r"(r[1]), "=r"(r[2]), "=r"(r[3]) : "r"(a));
}
__device__ __forceinline__ void ldm2(uint32_t* r, uint32_t a) {
    asm volatile("ldmatrix.sync.aligned.m8n8.x2.shared.b16 {%0,%1}, [%2];"
                 : "=r"(r[0]), "=r"(r[1]) : "r"(a));
}
__device__ __forceinline__ void ldm2t(uint32_t* r, uint32_t a) {
    asm volatile("ldmatrix.sync.aligned.m8n8.x2.trans.shared.b16 {%0,%1}, [%2];"
                 : "=r"(r[0]), "=r"(r[1]) : "r"(a));
}
__device__ __forceinline__ void mma_bf16(float* d, const uint32_t* a, const uint32_t* b) {
    asm volatile(
        "mma.sync.aligned.m16n8k16.row.col.f32.bf16.bf16.f32 "
        "{%0,%1,%2,%3}, {%4,%5,%6,%7}, {%8,%9}, {%0,%1,%2,%3};"
        : "+f"(d[0]), "+f"(d[1]), "+f"(d[2]), "+f"(d[3])
        : "r"(a[0]), "r"(a[1]), "r"(a[2]), "r"(a[3]), "r"(b[0]), "r"(b[1]));
}
// pack two fp32 -> bf16x2 reg; and hi/lo split of a pair
__device__ __forceinline__ uint32_t packbf(float a, float b) {
    __nv_bfloat162 t = __floats2bfloat162_rn(a, b);
    return *(uint32_t*)&t;
}
__device__ __forceinline__ void split2(float a, float b, uint32_t& h, uint32_t& l) {
    __nv_bfloat16 ha = __float2bfloat16(a), hb = __float2bfloat16(b);
    __nv_bfloat162 H = __halves2bfloat162(ha, hb);
    h = *(uint32_t*)&H;
    l = packbf(a - __bfloat162float(ha), b - __bfloat162float(hb));
}

// ---------------------------------------------------------------------------
// Prep: normalize padding mask -> byte mask + 64-bit valid bitmaps; causal_start
// ---------------------------------------------------------------------------
__global__ void k_prep(const unsigned char* __restrict__ mraw,
                       const int* __restrict__ csp) {
    __shared__ int s_byte;
    const int tid = threadIdx.x;
    if (tid == 0) {
        int v = csp[0];
        if (v < 0 || v > NN) {
            float f = __int_as_float(v);
            v = (int)f;
            if (v < 0) v = 0;
            if (v > NN) v = NN;
        }
        g_cs = v;
        s_byte = 0;
    }
    __syncthreads();
    int any = 0;
    for (int i = tid; i < BB*NN; i += 256) any |= mraw[i];
    if (any) atomicOr(&s_byte, 1);
    __syncthreads();
    const int bytemode = s_byte;
    const int* mw = (const int*)mraw;
    for (int e = tid; e < BB*NN; e += 256) {
        unsigned char p = bytemode ? (unsigned char)(mraw[e] != 0)
                                   : (unsigned char)(mw[e] != 0);
        g_mask[e] = p;
    }
    __syncthreads();
    for (int t = tid; t < BB*NTILES; t += 256) {
        const int b = t / NTILES, kt = t % NTILES;
        unsigned long long bits = 0ull;
        #pragma unroll 8
        for (int j = 0; j < 64; j++)
            if (g_mask[b*NN + kt*64 + j] == 0) bits |= (1ull << j);
        g_mbits[t] = bits;
    }
}

// ---------------------------------------------------------------------------
// fp32 -> bf16 hi/lo split
// ---------------------------------------------------------------------------
__global__ void k_split(const float4* __restrict__ src,
                        __nv_bfloat162* __restrict__ hi,
                        __nv_bfloat162* __restrict__ lo) {
    const int i = blockIdx.x * 256 + threadIdx.x;
    const float4 v = src[i];
    const __nv_bfloat16 h0 = __float2bfloat16(v.x), h1 = __float2bfloat16(v.y),
                        h2 = __float2bfloat16(v.z), h3 = __float2bfloat16(v.w);
    const __nv_bfloat16 l0 = __float2bfloat16(v.x - __bfloat162float(h0)),
                        l1 = __float2bfloat16(v.y - __bfloat162float(h1)),
                        l2 = __float2bfloat16(v.z - __bfloat162float(h2)),
                        l3 = __float2bfloat16(v.w - __bfloat162float(h3));
    hi[2*i]   = __halves2bfloat162(h0, h1);
    hi[2*i+1] = __halves2bfloat162(h2, h3);
    lo[2*i]   = __halves2bfloat162(l0, l1);
    lo[2*i+1] = __halves2bfloat162(l2, l3);
}

// ---------------------------------------------------------------------------
// HMMA GEMM (as R7): C = A * B^T via bf16 hi/lo 3-MMA. CTA 128x128, BK=64.
// mode 0: qkv epilogue -> q scaled hi/lo (b,h,n,d); k/v fp32 present + hi/lo
// mode 1: proj epilogue -> out = C + bias
// ---------------------------------------------------------------------------
#define TILE_B 16384
#define STAGE_B (4*TILE_B)

__global__ void __launch_bounds__(256, 1)
k_mma_gemm(const __nv_bfloat16* __restrict__ gAh, const __nv_bfloat16* __restrict__ gAl,
           const __nv_bfloat16* __restrict__ gBh, const __nv_bfloat16* __restrict__ gBl,
           const float* __restrict__ bias, float* __restrict__ outp, int mode) {
    extern __shared__ __align__(16) unsigned char dsm[];
    const int tid = threadIdx.x;
    const int lane = tid & 31, wid = tid >> 5;
    const int warpM = wid & 1, warpN = wid >> 1;
    const int m0 = blockIdx.y * 128, n0 = blockIdx.x * 128;

    const uint32_t dyn0 = smem_u32(dsm);
    const uint32_t sbase = (dyn0 + 1023) & ~1023u;

    const int lrow = tid >> 1;
    const int lcj0 = (tid & 1) * 4;
    const __nv_bfloat16* gptr[4] = {
        gAh + (size_t)(m0 + lrow) * CC, gAl + (size_t)(m0 + lrow) * CC,
        gBh + (size_t)(n0 + lrow) * CC, gBl + (size_t)(n0 + lrow) * CC };
    uint32_t soff[4][4];
    #pragma unroll
    for (int t = 0; t < 4; t++)
        #pragma unroll
        for (int j = 0; j < 4; j++)
            soff[t][j] = (uint32_t)(t * TILE_B + lrow * 128
                                    + (((lcj0 + j) ^ (lrow & 7)) << 4));

    const int la = lane & 15, ka = lane >> 4;
    const int lb = lane & 7, kb2 = (lane >> 3) & 1;
    const int arow = warpM * 64 + la;
    const int brow = warpN * 32 + lb;
    const int ax = arow & 7, bx = brow & 7;

    float acc[4][4][4];
    #pragma unroll
    for (int mf = 0; mf < 4; mf++)
        #pragma unroll
        for (int nf = 0; nf < 4; nf++)
            #pragma unroll
            for (int i = 0; i < 4; i++) acc[mf][nf][i] = 0.f;

    #pragma unroll
    for (int t = 0; t < 4; t++)
        #pragma unroll
        for (int j = 0; j < 4; j++)
            cpasync16(sbase + soff[t][j], gptr[t] + (lcj0 + j) * 8);
    cp_commit();

    for (int kb = 0; kb < NKB; kb++) {
        if (kb + 1 < NKB) {
            const uint32_t st = (uint32_t)((kb + 1) & 1) * STAGE_B;
            const size_t ko = (size_t)(kb + 1) * 64;
            #pragma unroll
            for (int t = 0; t < 4; t++)
                #pragma unroll
                for (int j = 0; j < 4; j++)
                    cpasync16(sbase + st + soff[t][j], gptr[t] + ko + (lcj0 + j) * 8);
            cp_commit();
            cp_wait<1>();
        } else {
            cp_wait<0>();
        }
        __syncthreads();

        const uint32_t buf = sbase + (uint32_t)(kb & 1) * STAGE_B;
        const uint32_t aAh = buf, aAl = buf + TILE_B;
        const uint32_t aBh = buf + 2*TILE_B, aBl = buf + 3*TILE_B;

        #pragma unroll
        for (int ks = 0; ks < 4; ks++) {
            const int kcB = ks * 2 + kb2;
            uint32_t Bh[4][2], Bl[4][2];
            #pragma unroll
            for (int nf = 0; nf < 4; nf++) {
                const uint32_t off = (uint32_t)((brow + nf*8) * 128 + ((kcB ^ bx) << 4));
                ldm2(Bh[nf], aBh + off);
                ldm2(Bl[nf], aBl + off);
            }
            const int kcA = ks * 2 + ka;
            #pragma unroll
            for (int mf = 0; mf < 4; mf++) {
                const uint32_t off = (uint32_t)((arow + mf*16) * 128 + ((kcA ^ ax) << 4));
                uint32_t Ah[4], Al[4];
                ldm4(Ah, aAh + off);
                ldm4(Al, aAl + off);
                #pragma unroll
                for (int nf = 0; nf < 4; nf++) {
                    mma_bf16(acc[mf][nf], Ah, Bh[nf]);
                    mma_bf16(acc[mf][nf], Ah, Bl[nf]);
                    mma_bf16(acc[mf][nf], Al, Bh[nf]);
                }
            }
        }
        __syncthreads();
    }

    #pragma unroll
    for (int mf = 0; mf < 4; mf++) {
        #pragma unroll
        for (int nf = 0; nf < 4; nf++) {
            const float* a = acc[mf][nf];
            const int col = n0 + warpN*32 + nf*8 + 2*(lane & 3);
            const int m_  = m0 + warpM*64 + mf*16 + (lane >> 2);
            if (mode == 0) {
                const int s = col >> 10, h = (col >> 6) & 15, d0 = col & 63;
                const size_t hb = (size_t)((m_ >> 11) * HH + h) * NN;
                const size_t i1 = (hb + (m_ & (NN-1))) * HD + d0;
                const size_t i2 = i1 + 8 * HD;
                if (s == 0) {
                    uint32_t h1, l1, h2, l2;
                    split2(a[0]*0.125f, a[1]*0.125f, h1, l1);
                    split2(a[2]*0.125f, a[3]*0.125f, h2, l2);
                    *(uint32_t*)(g_qh + i1) = h1; *(uint32_t*)(g_ql + i1) = l1;
                    *(uint32_t*)(g_qh + i2) = h2; *(uint32_t*)(g_ql + i2) = l2;
                } else {
                    float* pres = outp + OUT_ATTN + (size_t)(s - 1) * PRES_HALF;
                    *(float2*)(pres + i1) = make_float2(a[0], a[1]);
                    *(float2*)(pres + i2) = make_float2(a[2], a[3]);
                    __nv_bfloat16* bh_ = (s == 1) ? g_kh : g_vh;
                    __nv_bfloat16* bl_ = (s == 1) ? g_kl : g_vl;
                    uint32_t h1, l1, h2, l2;
                    split2(a[0], a[1], h1, l1);
                    split2(a[2], a[3], h2, l2);
                    *(uint32_t*)(bh_ + i1) = h1; *(uint32_t*)(bl_ + i1) = l1;
                    *(uint32_t*)(bh_ + i2) = h2; *(uint32_t*)(bl_ + i2) = l2;
                }
            } else {
                const float2 bz = *(const float2*)(bias + col);
                *(float2*)(outp + (size_t)m_ * CC + col) =
                    make_float2(a[0] + bz.x, a[1] + bz.y);
                *(float2*)(outp + (size_t)(m_ + 8) * CC + col) =
                    make_float2(a[2] + bz.x, a[3] + bz.y);
            }
        }
    }
}

// ---------------------------------------------------------------------------
// HMMA flash attention. BM=128 (8 warps x 16 rows), BN=64, hd=64.
// Q hi/lo fragments register-resident; K/V hi/lo double-buffered cp.async.
// S: 3-pass hi/lo. PV: 3-pass hi/lo, P repacked in registers, V^T via ldm.trans.
// Output written directly as bf16 hi/lo proj operands (g_ah/g_al).
// ---------------------------------------------------------------------------
#define AQ_B 16384                // one 128x64 bf16 tile
#define AST_B (4*8192)            // stage: Kh,Kl,Vh,Vl (64x64 each)

__global__ void __launch_bounds__(256, 1) k_attn_mma() {
    extern __shared__ __align__(16) unsigned char dsm[];
    const int tid = threadIdx.x;
    const int lane = tid & 31, w = tid >> 5;
    const int qs = blockIdx.x * 128, h = blockIdx.y, b = blockIdx.z;
    const int bh = b * HH + h;
    const int cs = g_cs;

    const uint32_t dyn0 = smem_u32(dsm);
    const uint32_t base = (dyn0 + 127) & ~127u;
    const uint32_t QH = base, QL = base + AQ_B, ST = base + 2*AQ_B;

    // ---- issue Q loads (group 0) ----
    {
        const int r = tid >> 1;
        const int c0 = (tid & 1) * 4;
        const __nv_bfloat16* qh = g_qh + ((size_t)bh * NN + qs + r) * HD;
        const __nv_bfloat16* ql = g_ql + ((size_t)bh * NN + qs + r) * HD;
        #pragma unroll
        for (int j = 0; j < 4; j++) {
            const int c = c0 + j;
            const uint32_t so = (uint32_t)(r * 128 + ((c ^ (r & 7)) << 4));
            cpasync16(QH + so, qh + c * 8);
            cpasync16(QL + so, ql + c * 8);
        }
        cp_commit();
    }

    // stage loader: Kh,Kl,Vh,Vl for tile kt into stage stg
    const int srow = tid >> 2, sc0 = (tid & 3) * 2;
    auto load_stage = [&](int stg, int kt) {
        const size_t go = ((size_t)bh * NN + kt * 64 + srow) * HD;
        const __nv_bfloat16* srcs[4] = { g_kh + go, g_kl + go, g_vh + go, g_vl + go };
        const uint32_t sb = ST + (uint32_t)stg * AST_B;
        #pragma unroll
        for (int t = 0; t < 4; t++)
            #pragma unroll
            for (int j = 0; j < 2; j++) {
                const int c = sc0 + j;
                const uint32_t so = (uint32_t)(srow * 128 + ((c ^ (srow & 7)) << 4));
                cpasync16(sb + t * 8192 + so, srcs[t] + c * 8);
            }
        cp_commit();
    };
    load_stage(0, 0);

    // ---- extract Q fragments ----
    cp_wait<1>();           // Q done (stage0 may still be in flight)
    __syncthreads();
    uint32_t Qh[4][4], Ql[4][4];
    {
        const int la = lane & 15, ka = lane >> 4;
        const int qr = w * 16 + la;
        #pragma unroll
        for (int ks = 0; ks < 4; ks++) {
            const int c = ks * 2 + ka;
            const uint32_t off = (uint32_t)(qr * 128 + ((c ^ (qr & 7)) << 4));
            ldm4(Qh[ks], QH + off);
            ldm4(Ql[ks], QL + off);
        }
    }

    float O[8][4];
    #pragma unroll
    for (int nf = 0; nf < 8; nf++)
        #pragma unroll
        for (int i = 0; i < 4; i++) O[nf][i] = 0.f;
    float m_i[2] = {-1e30f, -1e30f}, l_i[2] = {0.f, 0.f};

    const int lb = lane & 7, kb2 = (lane >> 3) & 1;
    const int t2 = 2 * (lane & 3);
    const int iq0 = qs + w * 16 + (lane >> 2);

    int kend = (qs >> 6) + 2;
    const int kc = (cs + 63) >> 6;
    if (kc > kend) kend = kc;
    if (kend > NTILES) kend = NTILES;

    for (int kt = 0; kt < kend; kt++) {
        if (kt + 1 < kend) { load_stage((kt + 1) & 1, kt + 1); cp_wait<1>(); }
        else               { cp_wait<0>(); }
        __syncthreads();

        const uint32_t buf = ST + (uint32_t)(kt & 1) * AST_B;

        // ---- S = Q K^T (3-pass hi/lo) ----
        float S[8][4];
        #pragma unroll
        for (int nf = 0; nf < 8; nf++)
            #pragma unroll
            for (int i = 0; i < 4; i++) S[nf][i] = 0.f;
        #pragma unroll
        for (int ks = 0; ks < 4; ks++) {
            const int c = ks * 2 + kb2;
            #pragma unroll
            for (int nf = 0; nf < 8; nf++) {
                const int r = nf * 8 + lb;
                const uint32_t off = (uint32_t)(r * 128 + ((c ^ (r & 7)) << 4));
                uint32_t Bh[2], Bl[2];
                ldm2(Bh, buf + off);          // Kh
                ldm2(Bl, buf + 8192 + off);   // Kl
                mma_bf16(S[nf], Qh[ks], Bh);
                mma_bf16(S[nf], Qh[ks], Bl);
                mma_bf16(S[nf], Ql[ks], Bh);
            }
        }

        // ---- mask ----
        const unsigned long long mb = g_mbits[b * NTILES + kt];
        const int jb = kt * 64;
        #pragma unroll
        for (int nf = 0; nf < 8; nf++) {
            const int jj0 = nf * 8 + t2, jj1 = jj0 + 1;
            const int j0 = jb + jj0, j1 = jb + jj1;
            const bool v0 = (mb >> jj0) & 1, v1 = (mb >> jj1) & 1;
            if (!(v0 && (j0 <= iq0     || j0 < cs))) S[nf][0] = -1e30f;
            if (!(v1 && (j1 <= iq0     || j1 < cs))) S[nf][1] = -1e30f;
            if (!(v0 && (j0 <= iq0 + 8 || j0 < cs))) S[nf][2] = -1e30f;
            if (!(v1 && (j1 <= iq0 + 8 || j1 < cs))) S[nf][3] = -1e30f;
        }

        // ---- online softmax (rows r, r+8; 4-lane groups) ----
        float alpha[2];
        #pragma unroll
        for (int r = 0; r < 2; r++) {
            float mloc = -1e30f;
            #pragma unroll
            for (int nf = 0; nf < 8; nf++)
                mloc = fmaxf(mloc, fmaxf(S[nf][2*r], S[nf][2*r+1]));
            mloc = fmaxf(mloc, __shfl_xor_sync(0xffffffffu, mloc, 1));
            mloc = fmaxf(mloc, __shfl_xor_sync(0xffffffffu, mloc, 2));
            const float mnew = fmaxf(m_i[r], mloc);
            float sum = 0.f;
            #pragma unroll
            for (int nf = 0; nf < 8; nf++) {
                const float p0 = __expf(S[nf][2*r]   - mnew);
                const float p1 = __expf(S[nf][2*r+1] - mnew);
                S[nf][2*r] = p0; S[nf][2*r+1] = p1;
                sum += p0 + p1;
            }
            sum += __shfl_xor_sync(0xffffffffu, sum, 1);
            sum += __shfl_xor_sync(0xffffffffu, sum, 2);
            alpha[r] = __expf(m_i[r] - mnew);
            l_i[r] = l_i[r] * alpha[r] + sum;
            m_i[r] = mnew;
        }

        // ---- O = alpha*O + P V (3-pass hi/lo, P repacked in regs) ----
        #pragma unroll
        for (int nf = 0; nf < 8; nf++) {
            O[nf][0] *= alpha[0]; O[nf][1] *= alpha[0];
            O[nf][2] *= alpha[1]; O[nf][3] *= alpha[1];
        }
        #pragma unroll
        for (int ks = 0; ks < 4; ks++) {
            uint32_t Ph[4], Pl[4];
            split2(S[2*ks][0],   S[2*ks][1],   Ph[0], Pl[0]);
            split2(S[2*ks][2],   S[2*ks][3],   Ph[1], Pl[1]);
            split2(S[2*ks+1][0], S[2*ks+1][1], Ph[2], Pl[2]);
            split2(S[2*ks+1][2], S[2*ks+1][3], Ph[3], Pl[3]);
            const int vr = ks * 16 + (lane & 15);
            #pragma unroll
            for (int nf = 0; nf < 8; nf++) {
                const uint32_t off = (uint32_t)(vr * 128 + ((nf ^ (vr & 7)) << 4));
                uint32_t Bvh[2], Bvl[2];
                ldm2t(Bvh, buf + 16384 + off);   // Vh^T
                ldm2t(Bvl, buf + 24576 + off);   // Vl^T
                mma_bf16(O[nf], Ph, Bvh);
                mma_bf16(O[nf], Ph, Bvl);
                mma_bf16(O[nf], Pl, Bvh);
            }
        }
        __syncthreads();
    }

    // ---- finalize: write hi/lo proj operands ----
    const float inv0 = (l_i[0] > 0.f) ? 1.f / l_i[0] : 0.f;
    const float inv1 = (l_i[1] > 0.f) ? 1.f / l_i[1] : 0.f;
    const size_t r1 = (size_t)(b * NN + qs + w * 16 + (lane >> 2)) * CC;
    const size_t r2 = r1 + 8 * CC;
    const int colb = h * HD + t2;
    #pragma unroll
    for (int nf = 0; nf < 8; nf++) {
        const size_t c = colb + nf * 8;
        uint32_t hh, ll;
        split2(O[nf][0] * inv0, O[nf][1] * inv0, hh, ll);
        *(uint32_t*)(g_ah + r1 + c) = hh; *(uint32_t*)(g_al + r1 + c) = ll;
        split2(O[nf][2] * inv1, O[nf][3] * inv1, hh, ll);
        *(uint32_t*)(g_ah + r2 + c) = hh; *(uint32_t*)(g_al + r2 + c) = ll;
    }
}

// ---------------------------------------------------------------------------
extern "C" void kernel_launch(void* const* d_in, const int* in_sizes, int n_in,
                              void* d_out, int out_size) {
    (void)in_sizes; (void)n_in; (void)out_size;
    const float* x      = (const float*)d_in[0];
    const unsigned char* mask = (const unsigned char*)d_in[1];
    const int*   csp    = (const int*)d_in[2];
    const float* w_qkv  = (const float*)d_in[3];
    const float* w_proj = (const float*)d_in[4];
    const float* b_proj = (const float*)d_in[5];
    float* outp = (float*)d_out;

    const int DSM_G = 2 * STAGE_B + 1024;              // 132 KB (GEMM)
    const int DSM_A = 2 * AQ_B + 2 * AST_B + 256;      // ~96.25 KB (attention)
    cudaFuncSetAttribute((const void*)k_mma_gemm,
                         cudaFuncAttributeMaxDynamicSharedMemorySize, DSM_G);
    cudaFuncSetAttribute((const void*)k_attn_mma,
                         cudaFuncAttributeMaxDynamicSharedMemorySize, DSM_A);

    __nv_bfloat16 *xh, *xl, *wqh, *wql, *wph, *wpl, *ah, *al;
    cudaGetSymbolAddress((void**)&xh,  g_xh);  cudaGetSymbolAddress((void**)&xl,  g_xl);
    cudaGetSymbolAddress((void**)&wqh, g_wqh); cudaGetSymbolAddress((void**)&wql, g_wql);
    cudaGetSymbolAddress((void**)&wph, g_wph); cudaGetSymbolAddress((void**)&wpl, g_wpl);
    cudaGetSymbolAddress((void**)&ah,  g_ah);  cudaGetSymbolAddress((void**)&al,  g_al);

    k_prep<<<1, 256>>>(mask, csp);

    k_split<<<MTOT*CC/1024, 256>>>((const float4*)x,
                                   (__nv_bfloat162*)xh, (__nv_bfloat162*)xl);
    k_split<<<QKVN*CC/1024, 256>>>((const float4*)w_qkv,
                                   (__nv_bfloat162*)wqh, (__nv_bfloat162*)wql);
    k_split<<<CC*CC/1024, 256>>>((const float4*)w_proj,
                                 (__nv_bfloat162*)wph, (__nv_bfloat162*)wpl);

    dim3 g1(QKVN / 128, MTOT / 128);          // (24, 32)
    k_mma_gemm<<<g1, 256, DSM_G>>>(xh, xl, wqh, wql, nullptr, outp, 0);

    dim3 ga(NN / 128, HH, BB);                // (16, 16, 2)
    k_attn_mma<<<ga, 256, DSM_A>>>();

    dim3 g2(CC / 128, MTOT / 128);            // (8, 32)
    k_mma_gemm<<<g2, 256, DSM_G>>>(ah, al, wph, wpl, b_proj, outp, 1);
}